// round 14
// baseline (speedup 1.0000x reference)
#include <cuda_runtime.h>
#include <cuda_fp16.h>
#include <math.h>
#include <stdint.h>

#define BATCH 2
#define SEQ   4096
#define EMB   512
#define NH    8
#define HD    64
#define BHTOT (BATCH*NH)
#define NROWS (BATCH*SEQ)
#define NE    (NROWS*EMB)
#define WE    (EMB*EMB)

// ---------------- scratch ----------------
__device__ __half g_Xh[3*NE];
__device__ __half g_Wh[4*WE];
__device__ __half g_Qh[BHTOT*SEQ*HD];    // [bh][s][hd]
__device__ __half g_Kh[BHTOT*SEQ*HD];    // [bh][s][hd]
__device__ __half g_Vh[BHTOT*SEQ*HD];    // [bh][s][hd]
__device__ __half g_ctxh[NROWS*EMB];
__device__ __half g_maskh[NROWS];        // 0 or -inf
__device__ int    g_tileskip[BATCH*64];
__device__ float2 g_rope[SEQ*32];        // (cos, sin)

// ---------------- helpers ----------------
__device__ __forceinline__ uint32_t smem_u32(const void* p){
    uint32_t a; asm("{ .reg .u64 t; cvta.to.shared.u64 t, %1; cvt.u32.u64 %0, t; }":"=r"(a):"l"(p)); return a;
}
__device__ __forceinline__ uint32_t h2pack(float lo, float hi){
    uint32_t d; asm("cvt.rn.f16x2.f32 %0, %1, %2;":"=r"(d):"f"(hi),"f"(lo)); return d;
}
__device__ __forceinline__ uint32_t hadd2(uint32_t a, uint32_t b){
    uint32_t d; asm("add.rn.f16x2 %0, %1, %2;":"=r"(d):"r"(a),"r"(b)); return d;
}
__device__ __forceinline__ uint32_t ex2h2(uint32_t a){
    uint32_t d; asm("ex2.approx.f16x2 %0, %1;":"=r"(d):"r"(a)); return d;
}
__device__ __forceinline__ void cp16(uint32_t d, const void* s){
    asm volatile("cp.async.cg.shared.global [%0], [%1], 16;"::"r"(d),"l"(s)); }
__device__ __forceinline__ void cp4(uint32_t d, const void* s){
    asm volatile("cp.async.ca.shared.global [%0], [%1], 4;"::"r"(d),"l"(s)); }
#define CP_COMMIT() asm volatile("cp.async.commit_group;":::"memory")
#define CP_WAIT1()  asm volatile("cp.async.wait_group 1;":::"memory")

#define HMMA(c,a,b0,b1) asm volatile( \
    "mma.sync.aligned.m16n8k16.row.col.f32.f16.f16.f32 " \
    "{%0,%1,%2,%3},{%4,%5,%6,%7},{%8,%9},{%0,%1,%2,%3};" \
    : "+f"((c)[0]),"+f"((c)[1]),"+f"((c)[2]),"+f"((c)[3]) \
    : "r"((a)[0]),"r"((a)[1]),"r"((a)[2]),"r"((a)[3]),"r"(b0),"r"(b1))

#define LDSM4(R0,R1,R2,R3,A) asm volatile( \
    "ldmatrix.sync.aligned.m8n8.x4.shared.b16 {%0,%1,%2,%3}, [%4];" \
    : "=r"(R0),"=r"(R1),"=r"(R2),"=r"(R3) : "r"(A))
#define LDSM4_T(R0,R1,R2,R3,A) asm volatile( \
    "ldmatrix.sync.aligned.m8n8.x4.trans.shared.b16 {%0,%1,%2,%3}, [%4];" \
    : "=r"(R0),"=r"(R1),"=r"(R2),"=r"(R3) : "r"(A))

extern __shared__ char dynsm[];

// ---------------- fused converts + rope table + mask ----------------
#define NIN (3*(NE/4))
#define NW  (4*(WE/4))
#define NT  (SEQ*32)
__global__ void convert_all(const float* __restrict__ q, const float* __restrict__ k,
                            const float* __restrict__ v, const float* __restrict__ wq,
                            const float* __restrict__ wk, const float* __restrict__ wv,
                            const float* __restrict__ wo, const unsigned char* __restrict__ mraw){
    if (blockIdx.x == gridDim.x-1){
        __shared__ int flag;
        if (threadIdx.x==0) flag=0;
        __syncthreads();
        int any=0;
        for (int i=threadIdx.x;i<NROWS;i+=blockDim.x) any |= (mraw[i]!=0);
        if (any) atomicOr(&flag,1);
        __syncthreads();
        const int bytemode=flag; const int* mi=(const int*)mraw;
        for (int i=threadIdx.x;i<NROWS;i+=blockDim.x){
            bool m = bytemode ? (mraw[i]!=0) : (mi[i]!=0);
            g_maskh[i] = __float2half(m ? -1e30f : 0.0f);
        }
        if (threadIdx.x < BATCH*64){
            int b = threadIdx.x>>6, t = threadIdx.x&63;
            int all = 1;
            for (int j=0;j<64;j++){
                int i = b*SEQ + t*64 + j;
                bool m = bytemode ? (mraw[i]!=0) : (mi[i]!=0);
                all &= (int)m;
            }
            g_tileskip[threadIdx.x] = all;
        }
        return;
    }
    int idx = blockIdx.x*blockDim.x + threadIdx.x;
    if (idx < NIN){
        int seg = idx / (NE/4), off = idx % (NE/4);
        const float* src = seg==0? q : (seg==1? k : v);
        float4 x = ((const float4*)src)[off];
        __half2* d = (__half2*)(g_Xh + (size_t)seg*NE + (size_t)off*4);
        d[0] = __floats2half2_rn(x.x, x.y);
        d[1] = __floats2half2_rn(x.z, x.w);
    } else if (idx < NIN+NW){
        int j = idx - NIN;
        int seg = j / (WE/4), off = j % (WE/4);
        const float* src = seg==0?wq:(seg==1?wk:(seg==2?wv:wo));
        float4 x = ((const float4*)src)[off];
        __half2* d = (__half2*)(g_Wh + (size_t)seg*WE + (size_t)off*4);
        d[0] = __floats2half2_rn(x.x, x.y);
        d[1] = __floats2half2_rn(x.z, x.w);
    } else if (idx < NIN+NW+NT){
        int j = idx - NIN - NW;
        int i = j & 31, s = j >> 5;
        float inv = exp2f(-(float)i * 0.41524101186097f);
        float sn, cs; __sincosf((float)s*inv, &sn, &cs);
        g_rope[j] = make_float2(cs, sn);
    }
}

// ================= fp16 GEMM core (unchanged) =================
#define HG_SMEM 110592

__device__ __forceinline__ void hg_load(uint32_t sb, const __half* X, const __half* W,
                                        int rowbase, int colbase, int kt, int tid, int st){
#pragma unroll
    for (int p=0;p<4;p++){
        int idx = tid + p*256;
        int r = idx>>3, ch = idx&7;
        cp16(sb + st*18432 + r*144 + ch*16, X + (size_t)(rowbase+r)*EMB + kt*64 + ch*8);
        cp16(sb + 55296 + st*18432 + r*144 + ch*16, W + (size_t)(colbase+r)*EMB + kt*64 + ch*8);
    }
}

__device__ __forceinline__ void hgemm_core(const __half* __restrict__ X,
                                           const __half* __restrict__ W,
                                           const float* __restrict__ bias,
                                           void* __restrict__ out, int mode)
{
    const uint32_t sb = smem_u32(dynsm);
    const int tid=threadIdx.x, wid=tid>>5, lane=tid&31;
    const int g = lane>>2, q4 = lane&3;
    const int wm = wid&1, wn = wid>>1;
    const int quad = lane>>3;
    const int rowbase = blockIdx.y*128, colbase = blockIdx.x*128;

    const uint32_t aoff = (uint32_t)((wm*64 + (lane&15))*144 + (lane>>4)*16);
    const uint32_t boff = (uint32_t)((wn*32 + ((quad>>1)&1)*8 + (lane&7))*144 + (quad&1)*16);

    hg_load(sb, X, W, rowbase, colbase, 0, tid, 0); CP_COMMIT();
    hg_load(sb, X, W, rowbase, colbase, 1, tid, 1); CP_COMMIT();

    float acc[4][4][4];
#pragma unroll
    for (int mi=0;mi<4;mi++)
#pragma unroll
        for (int ji=0;ji<4;ji++)
#pragma unroll
            for (int x=0;x<4;x++) acc[mi][ji][x]=0.f;

    int st = 0;
    for (int kt=0;kt<8;kt++){
        CP_WAIT1();
        __syncthreads();
        const uint32_t xa = sb + st*18432 + aoff;
        const uint32_t wa = sb + 55296 + st*18432 + boff;
#pragma unroll
        for (int c=0;c<4;c++){
            uint32_t a[4][4], bf[4][2];
#pragma unroll
            for (int mi=0;mi<4;mi++)
                LDSM4(a[mi][0],a[mi][1],a[mi][2],a[mi][3], xa + mi*2304 + c*32);
#pragma unroll
            for (int jp=0;jp<2;jp++)
                LDSM4(bf[2*jp][0],bf[2*jp][1],bf[2*jp+1][0],bf[2*jp+1][1], wa + jp*2304 + c*32);
#pragma unroll
            for (int mi=0;mi<4;mi++)
#pragma unroll
                for (int ji=0;ji<4;ji++)
                    HMMA(acc[mi][ji], a[mi], bf[ji][0], bf[ji][1]);
        }
        if (kt < 6){
            const int pb = (st+2>2)? st-1 : st+2;
            hg_load(sb, X, W, rowbase, colbase, kt+2, tid, pb);
        }
        CP_COMMIT();
        st = (st+1==3)? 0 : st+1;
    }

#pragma unroll
    for (int mi=0;mi<4;mi++){
        const int r0 = rowbase + wm*64 + mi*16 + g;
#pragma unroll
        for (int ji=0;ji<4;ji++){
            const int e = colbase + wn*32 + ji*8 + 2*q4;
            float2 bv = *(const float2*)(bias + e);
#pragma unroll
            for (int half=0; half<2; half++){
                const int r = r0 + half*8;
                float vx = acc[mi][ji][2*half+0] + bv.x;
                float vy = acc[mi][ji][2*half+1] + bv.y;
                if (mode==1){
                    float2 v; v.x=vx; v.y=vy;
                    *(float2*)((float*)out + (size_t)r*EMB + e) = v;
                } else {
                    int bb_=r>>12, s=r&(SEQ-1), hh=e>>6, d=e&(HD-1);
                    *(__half2*)((__half*)out + (((size_t)(bb_*NH+hh))*SEQ+s)*HD + d)
                        = __floats2half2_rn(vx, vy);
                }
            }
        }
    }
}

__global__ __launch_bounds__(256,2)
void hgemm_qkv(const float* __restrict__ bq, const float* __restrict__ bk,
               const float* __restrict__ bv){
    const int z = blockIdx.z;
    const float* bias = (z==0)? bq : ((z==1)? bk : bv);
    void* out = (z==0)? (void*)g_Qh : ((z==1)? (void*)g_Kh : (void*)g_Vh);
    hgemm_core(g_Xh + (size_t)z*NE, g_Wh + (size_t)z*WE, bias, out, 0);
}

__global__ __launch_bounds__(256,2)
void hgemm_one(const __half* __restrict__ X, const __half* __restrict__ W,
               const float* __restrict__ bias, void* __restrict__ out, int mode){
    hgemm_core(X, W, bias, out, mode);
}

// ---------------- RoPE (table, half2-vectorized) ----------------
__global__ void rope_h(){
    const int total=BHTOT*SEQ*16;
    int gid=blockIdx.x*blockDim.x+threadIdx.x;
    if (gid>=total) return;
    int i2=gid&15, row=gid>>4, s=row&(SEQ-1);
    float2 t0 = g_rope[(s<<5)|(2*i2)];
    float2 t1 = g_rope[(s<<5)|(2*i2+1)];
    const float qs=0.125f*1.44269504f;
    size_t base=(size_t)row*HD + 2*i2;

    __half2 qa = *(__half2*)(g_Qh+base), qb = *(__half2*)(g_Qh+base+32);
    float2 fa = __half22float2(qa), fb = __half22float2(qb);
    *(__half2*)(g_Qh+base)    = __floats2half2_rn(qs*(fa.x*t0.x - fb.x*t0.y), qs*(fa.y*t1.x - fb.y*t1.y));
    *(__half2*)(g_Qh+base+32) = __floats2half2_rn(qs*(fb.x*t0.x + fa.x*t0.y), qs*(fb.y*t1.x + fa.y*t1.y));

    __half2 ka = *(__half2*)(g_Kh+base), kb = *(__half2*)(g_Kh+base+32);
    float2 ga = __half22float2(ka), gb = __half22float2(kb);
    *(__half2*)(g_Kh+base)    = __floats2half2_rn(ga.x*t0.x - gb.x*t0.y, ga.y*t1.x - gb.y*t1.y);
    *(__half2*)(g_Kh+base+32) = __floats2half2_rn(gb.x*t0.x + ga.x*t0.y, gb.y*t1.x + ga.y*t1.y);
}

// ========== flash attention: PV(i-1) interleaved with softmax(i) ==========
// SMEM: mb 3x128 @0, skip @512, Q @1024 (18432), K @19456 (3x9216), V @47104 (4x9216)
#define FQ_B   1024
#define FK_B   19456
#define FV_B   47104
#define FSMEM  83968
#define ONESH2 0x3C003C00u

__device__ __forceinline__ void f_loadK(uint32_t sb, int bh, int t, int tid, int st){
#pragma unroll
    for (int p=0;p<4;p++){
        int idx = tid + p*128;
        int r = idx>>3, ch = idx&7;
        cp16(sb + FK_B + st*9216 + r*144 + ch*16,
             g_Kh + ((size_t)bh*SEQ + t*64 + r)*HD + ch*8);
    }
}
__device__ __forceinline__ void f_loadV(uint32_t sb, int bh, int t, int tid, int st){
#pragma unroll
    for (int p=0;p<4;p++){
        int idx = tid + p*128;
        int r = idx>>3, ch = idx&7;
        cp16(sb + FV_B + st*9216 + r*144 + ch*16,
             g_Vh + ((size_t)bh*SEQ + t*64 + r)*HD + ch*8);
    }
}
__device__ __forceinline__ void f_loadMB(uint32_t sb, int b, int t, int tid, int st){
    if (tid < 32) cp4(sb + st*128 + tid*4, g_maskh + b*SEQ + t*64 + tid*2);
}

// One pipelined iteration: QK(I) -> [PV(I-1) || softmax(I)] -> prefetch(I+2)
#define FITER(I, PPREV, PCUR, SKPREV, SKCUR) do{                                   \
    CP_WAIT1(); __syncthreads();                                                    \
    SKCUR = ((const int*)dynsm)[128 + (I)];                                         \
    float s[2][8][4];                                                               \
    if (!(SKCUR)){                                                                  \
        const uint32_t kb = sb + FK_B + ((I)%3)*9216 + lofs;                        \
        _Pragma("unroll") for (int mi=0;mi<2;mi++)                                  \
        _Pragma("unroll") for (int j=0;j<8;j++)                                     \
        _Pragma("unroll") for (int x=0;x<4;x++) s[mi][j][x]=0.f;                    \
        _Pragma("unroll") for (int c=0;c<4;c++){                                    \
            uint32_t kf[8][2];                                                      \
            _Pragma("unroll") for (int jp=0;jp<4;jp++)                              \
                LDSM4(kf[2*jp][0],kf[2*jp][1],kf[2*jp+1][0],kf[2*jp+1][1],          \
                      kb + jp*2304 + c*32);                                         \
            _Pragma("unroll") for (int mi=0;mi<2;mi++)                              \
            _Pragma("unroll") for (int j=0;j<8;j++)                                 \
                HMMA(s[mi][j], qf[mi][c], kf[j][0], kf[j][1]);                      \
        }                                                                           \
    }                                                                               \
    const uint32_t vb = sb + FV_B + (((I)+3)&3)*9216 + lofsv;                       \
    const uint32_t* mbU = smU + ((I)%3)*32;                                         \
    const int dopv = ((I)>0) && !(SKPREV);                                          \
    _Pragma("unroll") for (int c=0;c<4;c++){                                        \
        if (dopv){                                                                  \
            uint32_t vf[8][2];                                                      \
            _Pragma("unroll") for (int jp=0;jp<4;jp++)                              \
                LDSM4_T(vf[2*jp][0],vf[2*jp][1],vf[2*jp+1][0],vf[2*jp+1][1],        \
                        vb + c*2304 + jp*32);                                       \
            _Pragma("unroll") for (int mi=0;mi<2;mi++){                             \
                uint32_t A[4] = {PPREV[mi][2*c][0], PPREV[mi][2*c][1],              \
                                 PPREV[mi][2*c+1][0], PPREV[mi][2*c+1][1]};         \
                _Pragma("unroll") for (int jn=0;jn<8;jn++)                          \
                    HMMA(o[mi][jn], A, vf[jn][0], vf[jn][1]);                       \
                HMMA(racc[mi], A, ONESH2, ONESH2);                                  \
            }                                                                       \
        }                                                                           \
        if (!(SKCUR)){                                                              \
            _Pragma("unroll") for (int jj=0;jj<2;jj++){                             \
                const int j = 2*c + jj;                                             \
                uint32_t mb2u = mbU[j*4 + q4];                                      \
                _Pragma("unroll") for (int mi=0;mi<2;mi++){                         \
                    PCUR[mi][j][0] = ex2h2(hadd2(h2pack(s[mi][j][0], s[mi][j][1]), mb2u)); \
                    PCUR[mi][j][1] = ex2h2(hadd2(h2pack(s[mi][j][2], s[mi][j][3]), mb2u)); \
                }                                                                   \
            }                                                                       \
        }                                                                           \
    }                                                                               \
    if ((I) < 62){                                                                  \
        f_loadK(sb, bh, (I)+2, tid, ((I)+2)%3);                                     \
        f_loadV(sb, bh, (I)+2, tid, ((I)+2)&3);                                     \
        f_loadMB(sb, b, (I)+2, tid, ((I)+2)%3);                                     \
    }                                                                               \
    CP_COMMIT();                                                                    \
}while(0)

__global__ __launch_bounds__(128,2) void flash_h()
{
    const uint32_t sb = smem_u32(dynsm);
    const uint32_t* smU = (const uint32_t*)dynsm;
    const int tid=threadIdx.x, wid=tid>>5, lane=tid&31;
    const int g = lane>>2, q4 = lane&3;
    const int quad = lane>>3;
    const int bh=blockIdx.y, b=bh>>3, h=bh&7;
    const int q0=blockIdx.x*128;

    const uint32_t lofs  = (uint32_t)((((quad>>1)&1)*8 + (lane&7))*144 + (quad&1)*16);
    const uint32_t lofsv = (uint32_t)(((quad&1)*8 + (lane&7))*144 + ((quad>>1)&1)*16);

#pragma unroll
    for (int p=0;p<8;p++){
        int idx = tid + p*128;
        int r = idx>>3, ch = idx&7;
        cp16(sb + FQ_B + r*144 + ch*16, g_Qh + ((size_t)bh*SEQ + q0 + r)*HD + ch*8);
    }
    if (tid < 64) cp4(sb + 512 + tid*4, g_tileskip + b*64 + tid);
    f_loadK(sb, bh, 0, tid, 0); f_loadV(sb, bh, 0, tid, 0); f_loadMB(sb, b, 0, tid, 0);
    CP_COMMIT();
    f_loadK(sb, bh, 1, tid, 1); f_loadV(sb, bh, 1, tid, 1); f_loadMB(sb, b, 1, tid, 1);
    CP_COMMIT();

    float o[2][8][4];
#pragma unroll
    for (int mi=0;mi<2;mi++)
#pragma unroll
        for (int j=0;j<8;j++)
#pragma unroll
            for (int x=0;x<4;x++) o[mi][j][x]=0.f;
    float racc[2][4];
#pragma unroll
    for (int mi=0;mi<2;mi++)
#pragma unroll
        for (int x=0;x<4;x++) racc[mi][x]=0.f;
    uint32_t qf[2][4][4];

    CP_WAIT1();
    __syncthreads();
    {
        const uint32_t* Qu = smU + FQ_B/4;
#pragma unroll
        for (int mi=0;mi<2;mi++)
#pragma unroll
            for (int c=0;c<4;c++){
                const uint32_t* qp = Qu + (wid*32 + mi*16 + g)*36 + c*8 + q4;
                qf[mi][c][0]=qp[0]; qf[mi][c][1]=qp[8*36];
                qf[mi][c][2]=qp[4]; qf[mi][c][3]=qp[8*36+4];
            }
    }

    uint32_t ppA[2][8][2], ppB[2][8][2];
    int skA = 1, skB = 1;

    for (int i=0;i<64;i+=2){
        FITER(i,   ppB, ppA, skB, skA);
        FITER(i+1, ppA, ppB, skA, skB);
    }

    // ---- peeled final PV(63): pp in ppB, V slot 63&3 = 3 ----
    if (!skB){
        const uint32_t vb = sb + FV_B + 3*9216 + lofsv;
#pragma unroll
        for (int c=0;c<4;c++){
            uint32_t vf[8][2];
#pragma unroll
            for (int jp=0;jp<4;jp++)
                LDSM4_T(vf[2*jp][0],vf[2*jp][1],vf[2*jp+1][0],vf[2*jp+1][1], vb + c*2304 + jp*32);
#pragma unroll
            for (int mi=0;mi<2;mi++){
                uint32_t A[4] = {ppB[mi][2*c][0], ppB[mi][2*c][1], ppB[mi][2*c+1][0], ppB[mi][2*c+1][1]};
#pragma unroll
                for (int jn=0;jn<8;jn++)
                    HMMA(o[mi][jn], A, vf[jn][0], vf[jn][1]);
                HMMA(racc[mi], A, ONESH2, ONESH2);
            }
        }
    }

    // ---- epilogue ----
#pragma unroll
    for (int mi=0;mi<2;mi++){
        const float inv0 = 1.0f/racc[mi][0], inv1 = 1.0f/racc[mi][2];
        const int row0 = q0 + wid*32 + mi*16 + g;
        __half* d0 = g_ctxh + ((size_t)(b*SEQ + row0  ))*EMB + h*HD;
        __half* d1 = g_ctxh + ((size_t)(b*SEQ + row0+8))*EMB + h*HD;
#pragma unroll
        for (int jn=0;jn<8;jn++){
            *(__half2*)(d0 + jn*8 + 2*q4) = __floats2half2_rn(o[mi][jn][0]*inv0, o[mi][jn][1]*inv0);
            *(__half2*)(d1 + jn*8 + 2*q4) = __floats2half2_rn(o[mi][jn][2]*inv1, o[mi][jn][3]*inv1);
        }
    }
}

// ---------------- launch ----------------
extern "C" void kernel_launch(void* const* d_in, const int* in_sizes, int n_in,
                              void* d_out, int out_size)
{
    const float* query=(const float*)d_in[0];
    const float* key_ =(const float*)d_in[1];
    const float* value=(const float*)d_in[2];
    const float* Wq=(const float*)d_in[3];  const float* bq=(const float*)d_in[4];
    const float* Wk=(const float*)d_in[5];  const float* bk=(const float*)d_in[6];
    const float* Wv=(const float*)d_in[7];  const float* bv=(const float*)d_in[8];
    const float* Wo=(const float*)d_in[9];  const float* bo=(const float*)d_in[10];
    const unsigned char* mask=(const unsigned char*)d_in[11];

    __half *Wh,*Ch;
    cudaGetSymbolAddress((void**)&Wh, g_Wh);
    cudaGetSymbolAddress((void**)&Ch, g_ctxh);

    cudaFuncSetAttribute(flash_h,   cudaFuncAttributeMaxDynamicSharedMemorySize, FSMEM);
    cudaFuncSetAttribute(hgemm_qkv, cudaFuncAttributeMaxDynamicSharedMemorySize, HG_SMEM);
    cudaFuncSetAttribute(hgemm_one, cudaFuncAttributeMaxDynamicSharedMemorySize, HG_SMEM);

    convert_all<<<(NIN+NW+NT+255)/256 + 1,256>>>(query, key_, value, Wq, Wk, Wv, Wo, mask);

    hgemm_qkv<<<dim3(EMB/128, NROWS/128, 3),256,HG_SMEM>>>(bq, bk, bv);

    rope_h<<<(BHTOT*SEQ*16+255)/256,256>>>();

    flash_h<<<dim3(SEQ/128, BHTOT), 128, FSMEM>>>();

    hgemm_one<<<dim3(EMB/128, NROWS/128),256,HG_SMEM>>>(Ch, Wh + 3*(size_t)WE, bo, d_out, 1);
}

// round 15
// speedup vs baseline: 1.6828x; 1.6828x over previous
#include <cuda_runtime.h>
#include <cuda_fp16.h>
#include <math.h>
#include <stdint.h>

#define BATCH 2
#define SEQ   4096
#define EMB   512
#define NH    8
#define HD    64
#define BHTOT (BATCH*NH)
#define NROWS (BATCH*SEQ)
#define NE    (NROWS*EMB)
#define WE    (EMB*EMB)

// ---------------- scratch ----------------
__device__ __half g_Xh[3*NE];
__device__ __half g_Wh[4*WE];
__device__ __half g_Qh[BHTOT*SEQ*HD];    // [bh][s][hd]
__device__ __half g_Kh[BHTOT*SEQ*HD];    // [bh][s][hd]
__device__ __half g_Vh[BHTOT*SEQ*HD];    // [bh][s][hd]
__device__ __half g_ctxh[NROWS*EMB];
__device__ __half g_maskh[NROWS];        // 0 or -inf
__device__ int    g_tileskip[BATCH*64];
__device__ float2 g_rope[SEQ*32];        // (cos, sin)

// ---------------- helpers ----------------
__device__ __forceinline__ uint32_t smem_u32(const void* p){
    uint32_t a; asm("{ .reg .u64 t; cvta.to.shared.u64 t, %1; cvt.u32.u64 %0, t; }":"=r"(a):"l"(p)); return a;
}
__device__ __forceinline__ uint32_t h2pack(float lo, float hi){
    uint32_t d; asm("cvt.rn.f16x2.f32 %0, %1, %2;":"=r"(d):"f"(hi),"f"(lo)); return d;
}
__device__ __forceinline__ uint32_t hadd2(uint32_t a, uint32_t b){
    uint32_t d; asm("add.rn.f16x2 %0, %1, %2;":"=r"(d):"r"(a),"r"(b)); return d;
}
__device__ __forceinline__ uint32_t ex2h2(uint32_t a){
    uint32_t d; asm("ex2.approx.f16x2 %0, %1;":"=r"(d):"r"(a)); return d;
}
__device__ __forceinline__ void cp16(uint32_t d, const void* s){
    asm volatile("cp.async.cg.shared.global [%0], [%1], 16;"::"r"(d),"l"(s)); }
__device__ __forceinline__ void cp4(uint32_t d, const void* s){
    asm volatile("cp.async.ca.shared.global [%0], [%1], 4;"::"r"(d),"l"(s)); }
#define CP_COMMIT() asm volatile("cp.async.commit_group;":::"memory")
#define CP_WAIT1()  asm volatile("cp.async.wait_group 1;":::"memory")

#define HMMA(c,a,b0,b1) asm volatile( \
    "mma.sync.aligned.m16n8k16.row.col.f32.f16.f16.f32 " \
    "{%0,%1,%2,%3},{%4,%5,%6,%7},{%8,%9},{%0,%1,%2,%3};" \
    : "+f"((c)[0]),"+f"((c)[1]),"+f"((c)[2]),"+f"((c)[3]) \
    : "r"((a)[0]),"r"((a)[1]),"r"((a)[2]),"r"((a)[3]),"r"(b0),"r"(b1))

#define LDSM4(R0,R1,R2,R3,A) asm volatile( \
    "ldmatrix.sync.aligned.m8n8.x4.shared.b16 {%0,%1,%2,%3}, [%4];" \
    : "=r"(R0),"=r"(R1),"=r"(R2),"=r"(R3) : "r"(A))
#define LDSM4_T(R0,R1,R2,R3,A) asm volatile( \
    "ldmatrix.sync.aligned.m8n8.x4.trans.shared.b16 {%0,%1,%2,%3}, [%4];" \
    : "=r"(R0),"=r"(R1),"=r"(R2),"=r"(R3) : "r"(A))

extern __shared__ char dynsm[];

// ---------------- fused converts + rope table + mask ----------------
#define NIN (3*(NE/4))
#define NW  (4*(WE/4))
#define NT  (SEQ*32)
__global__ void convert_all(const float* __restrict__ q, const float* __restrict__ k,
                            const float* __restrict__ v, const float* __restrict__ wq,
                            const float* __restrict__ wk, const float* __restrict__ wv,
                            const float* __restrict__ wo, const unsigned char* __restrict__ mraw){
    if (blockIdx.x == gridDim.x-1){
        __shared__ int flag;
        if (threadIdx.x==0) flag=0;
        __syncthreads();
        int any=0;
        for (int i=threadIdx.x;i<NROWS;i+=blockDim.x) any |= (mraw[i]!=0);
        if (any) atomicOr(&flag,1);
        __syncthreads();
        const int bytemode=flag; const int* mi=(const int*)mraw;
        for (int i=threadIdx.x;i<NROWS;i+=blockDim.x){
            bool m = bytemode ? (mraw[i]!=0) : (mi[i]!=0);
            g_maskh[i] = __float2half(m ? -1e30f : 0.0f);
        }
        if (threadIdx.x < BATCH*64){
            int b = threadIdx.x>>6, t = threadIdx.x&63;
            int all = 1;
            for (int j=0;j<64;j++){
                int i = b*SEQ + t*64 + j;
                bool m = bytemode ? (mraw[i]!=0) : (mi[i]!=0);
                all &= (int)m;
            }
            g_tileskip[threadIdx.x] = all;
        }
        return;
    }
    int idx = blockIdx.x*blockDim.x + threadIdx.x;
    if (idx < NIN){
        int seg = idx / (NE/4), off = idx % (NE/4);
        const float* src = seg==0? q : (seg==1? k : v);
        float4 x = ((const float4*)src)[off];
        __half2* d = (__half2*)(g_Xh + (size_t)seg*NE + (size_t)off*4);
        d[0] = __floats2half2_rn(x.x, x.y);
        d[1] = __floats2half2_rn(x.z, x.w);
    } else if (idx < NIN+NW){
        int j = idx - NIN;
        int seg = j / (WE/4), off = j % (WE/4);
        const float* src = seg==0?wq:(seg==1?wk:(seg==2?wv:wo));
        float4 x = ((const float4*)src)[off];
        __half2* d = (__half2*)(g_Wh + (size_t)seg*WE + (size_t)off*4);
        d[0] = __floats2half2_rn(x.x, x.y);
        d[1] = __floats2half2_rn(x.z, x.w);
    } else if (idx < NIN+NW+NT){
        int j = idx - NIN - NW;
        int i = j & 31, s = j >> 5;
        float inv = exp2f(-(float)i * 0.41524101186097f);
        float sn, cs; __sincosf((float)s*inv, &sn, &cs);
        g_rope[j] = make_float2(cs, sn);
    }
}

// ======= fp16 GEMM: 64x64 warp tiles (4 warps, 128 thr), BK=64, 3-stage =======
#define HG_SMEM 110592

__device__ __forceinline__ void hg_load(uint32_t sb, const __half* X, const __half* W,
                                        int rowbase, int colbase, int kt, int tid, int st){
#pragma unroll
    for (int p=0;p<8;p++){
        int idx = tid + p*128;            // 0..1023
        int r = idx>>3, ch = idx&7;
        cp16(sb + st*18432 + r*144 + ch*16, X + (size_t)(rowbase+r)*EMB + kt*64 + ch*8);
        cp16(sb + 55296 + st*18432 + r*144 + ch*16, W + (size_t)(colbase+r)*EMB + kt*64 + ch*8);
    }
}

__device__ __forceinline__ void hgemm_core(const __half* __restrict__ X,
                                           const __half* __restrict__ W,
                                           const float* __restrict__ bias,
                                           void* __restrict__ out, int mode)
{
    const uint32_t sb = smem_u32(dynsm);
    const int tid=threadIdx.x, wid=tid>>5, lane=tid&31;
    const int g = lane>>2, q4 = lane&3;
    const int wm = wid&1, wn = wid>>1;          // 2x2 warp grid, 64x64 each
    const int quad = lane>>3;
    const int rowbase = blockIdx.y*128, colbase = blockIdx.x*128;

    const uint32_t aoff = (uint32_t)((wm*64 + (lane&15))*144 + (lane>>4)*16);
    const uint32_t boff = (uint32_t)((wn*64 + ((quad>>1)&1)*8 + (lane&7))*144 + (quad&1)*16);

    hg_load(sb, X, W, rowbase, colbase, 0, tid, 0); CP_COMMIT();
    hg_load(sb, X, W, rowbase, colbase, 1, tid, 1); CP_COMMIT();

    float acc[4][8][4];
#pragma unroll
    for (int mi=0;mi<4;mi++)
#pragma unroll
        for (int ji=0;ji<8;ji++)
#pragma unroll
            for (int x=0;x<4;x++) acc[mi][ji][x]=0.f;

    int st = 0;
    for (int kt=0;kt<8;kt++){
        CP_WAIT1();
        __syncthreads();
        const uint32_t xa = sb + st*18432 + aoff;
        const uint32_t wa = sb + 55296 + st*18432 + boff;
#pragma unroll
        for (int c=0;c<4;c++){
            uint32_t a[4][4], bf[8][2];
#pragma unroll
            for (int mi=0;mi<4;mi++)
                LDSM4(a[mi][0],a[mi][1],a[mi][2],a[mi][3], xa + mi*2304 + c*32);
#pragma unroll
            for (int jp=0;jp<4;jp++)
                LDSM4(bf[2*jp][0],bf[2*jp][1],bf[2*jp+1][0],bf[2*jp+1][1], wa + jp*2304 + c*32);
#pragma unroll
            for (int mi=0;mi<4;mi++)
#pragma unroll
                for (int ji=0;ji<8;ji++)
                    HMMA(acc[mi][ji], a[mi], bf[ji][0], bf[ji][1]);
        }
        if (kt < 6){
            const int pb = (st+2>2)? st-1 : st+2;
            hg_load(sb, X, W, rowbase, colbase, kt+2, tid, pb);
        }
        CP_COMMIT();
        st = (st+1==3)? 0 : st+1;
    }

#pragma unroll
    for (int mi=0;mi<4;mi++){
        const int r0 = rowbase + wm*64 + mi*16 + g;
#pragma unroll
        for (int ji=0;ji<8;ji++){
            const int e = colbase + wn*64 + ji*8 + 2*q4;
            float2 bv = *(const float2*)(bias + e);
#pragma unroll
            for (int half=0; half<2; half++){
                const int r = r0 + half*8;
                float vx = acc[mi][ji][2*half+0] + bv.x;
                float vy = acc[mi][ji][2*half+1] + bv.y;
                if (mode==1){
                    float2 v; v.x=vx; v.y=vy;
                    *(float2*)((float*)out + (size_t)r*EMB + e) = v;
                } else {
                    int bb_=r>>12, s=r&(SEQ-1), hh=e>>6, d=e&(HD-1);
                    *(__half2*)((__half*)out + (((size_t)(bb_*NH+hh))*SEQ+s)*HD + d)
                        = __floats2half2_rn(vx, vy);
                }
            }
        }
    }
}

__global__ __launch_bounds__(128,2)
void hgemm_qkv(const float* __restrict__ bq, const float* __restrict__ bk,
               const float* __restrict__ bv){
    const int z = blockIdx.z;
    const float* bias = (z==0)? bq : ((z==1)? bk : bv);
    void* out = (z==0)? (void*)g_Qh : ((z==1)? (void*)g_Kh : (void*)g_Vh);
    hgemm_core(g_Xh + (size_t)z*NE, g_Wh + (size_t)z*WE, bias, out, 0);
}

__global__ __launch_bounds__(128,2)
void hgemm_one(const __half* __restrict__ X, const __half* __restrict__ W,
               const float* __restrict__ bias, void* __restrict__ out, int mode){
    hgemm_core(X, W, bias, out, mode);
}

// ---------------- RoPE (table, half2-vectorized) ----------------
__global__ void rope_h(){
    const int total=BHTOT*SEQ*16;
    int gid=blockIdx.x*blockDim.x+threadIdx.x;
    if (gid>=total) return;
    int i2=gid&15, row=gid>>4, s=row&(SEQ-1);
    float2 t0 = g_rope[(s<<5)|(2*i2)];
    float2 t1 = g_rope[(s<<5)|(2*i2+1)];
    const float qs=0.125f*1.44269504f;
    size_t base=(size_t)row*HD + 2*i2;

    __half2 qa = *(__half2*)(g_Qh+base), qb = *(__half2*)(g_Qh+base+32);
    float2 fa = __half22float2(qa), fb = __half22float2(qb);
    *(__half2*)(g_Qh+base)    = __floats2half2_rn(qs*(fa.x*t0.x - fb.x*t0.y), qs*(fa.y*t1.x - fb.y*t1.y));
    *(__half2*)(g_Qh+base+32) = __floats2half2_rn(qs*(fb.x*t0.x + fa.x*t0.y), qs*(fb.y*t1.x + fa.y*t1.y));

    __half2 ka = *(__half2*)(g_Kh+base), kb = *(__half2*)(g_Kh+base+32);
    float2 ga = __half22float2(ka), gb = __half22float2(kb);
    *(__half2*)(g_Kh+base)    = __floats2half2_rn(ga.x*t0.x - gb.x*t0.y, ga.y*t1.x - gb.y*t1.y);
    *(__half2*)(g_Kh+base+32) = __floats2half2_rn(gb.x*t0.x + ga.x*t0.y, gb.y*t1.x + ga.y*t1.y);
}

// ========== fp16 flash attention: R12 config (4 warps x 32 q-rows, 2 CTAs/SM) ==========
#define FQ_B   1024
#define FK_B   19456
#define FV_B   47104
#define FSMEM  74752
#define ONESH2 0x3C003C00u

__device__ __forceinline__ void f_loadK(uint32_t sb, int bh, int t, int tid, int st){
#pragma unroll
    for (int p=0;p<4;p++){
        int idx = tid + p*128;
        int r = idx>>3, ch = idx&7;
        cp16(sb + FK_B + st*9216 + r*144 + ch*16,
             g_Kh + ((size_t)bh*SEQ + t*64 + r)*HD + ch*8);
    }
}
__device__ __forceinline__ void f_loadV(uint32_t sb, int bh, int t, int tid, int st){
#pragma unroll
    for (int p=0;p<4;p++){
        int idx = tid + p*128;
        int r = idx>>3, ch = idx&7;
        cp16(sb + FV_B + st*9216 + r*144 + ch*16,
             g_Vh + ((size_t)bh*SEQ + t*64 + r)*HD + ch*8);
    }
}
__device__ __forceinline__ void f_loadMB(uint32_t sb, int b, int t, int tid, int st){
    if (tid < 32) cp4(sb + st*128 + tid*4, g_maskh + b*SEQ + t*64 + tid*2);
}

__global__ __launch_bounds__(128,2) void flash_h()
{
    const uint32_t sb = smem_u32(dynsm);
    const uint32_t* smU = (const uint32_t*)dynsm;
    const int tid=threadIdx.x, wid=tid>>5, lane=tid&31;
    const int g = lane>>2, q4 = lane&3;
    const int quad = lane>>3;
    const int bh=blockIdx.y, b=bh>>3, h=bh&7;
    const int q0=blockIdx.x*128;

    const uint32_t lofs  = (uint32_t)((((quad>>1)&1)*8 + (lane&7))*144 + (quad&1)*16);
    const uint32_t lofsv = (uint32_t)(((quad&1)*8 + (lane&7))*144 + ((quad>>1)&1)*16);

#pragma unroll
    for (int p=0;p<8;p++){
        int idx = tid + p*128;
        int r = idx>>3, ch = idx&7;
        cp16(sb + FQ_B + r*144 + ch*16, g_Qh + ((size_t)bh*SEQ + q0 + r)*HD + ch*8);
    }
    if (tid < 64) cp4(sb + 512 + tid*4, g_tileskip + b*64 + tid);
    f_loadK(sb, bh, 0, tid, 0); f_loadV(sb, bh, 0, tid, 0); f_loadMB(sb, b, 0, tid, 0);
    CP_COMMIT();
    f_loadK(sb, bh, 1, tid, 1); f_loadV(sb, bh, 1, tid, 1); f_loadMB(sb, b, 1, tid, 1);
    CP_COMMIT();

    float o[2][8][4];
#pragma unroll
    for (int mi=0;mi<2;mi++)
#pragma unroll
        for (int j=0;j<8;j++)
#pragma unroll
            for (int x=0;x<4;x++) o[mi][j][x]=0.f;
    float racc[2][4];
#pragma unroll
    for (int mi=0;mi<2;mi++)
#pragma unroll
        for (int x=0;x<4;x++) racc[mi][x]=0.f;
    uint32_t qf[2][4][4];

    CP_WAIT1();
    __syncthreads();
    {
        const uint32_t* Qu = smU + FQ_B/4;
#pragma unroll
        for (int mi=0;mi<2;mi++)
#pragma unroll
            for (int c=0;c<4;c++){
                const uint32_t* qp = Qu + (wid*32 + mi*16 + g)*36 + c*8 + q4;
                qf[mi][c][0]=qp[0]; qf[mi][c][1]=qp[8*36];
                qf[mi][c][2]=qp[4]; qf[mi][c][3]=qp[8*36+4];
            }
    }

    int cb = 0;
    for (int i=0;i<64;i++){
        CP_WAIT1();
        __syncthreads();

        const int skip = ((const int*)dynsm)[128 + i];
        if (!skip){
            // ---- S = Q K^T (K fragments shared across both m-frags) ----
            float s[2][8][4];
#pragma unroll
            for (int mi=0;mi<2;mi++)
#pragma unroll
                for (int j=0;j<8;j++)
#pragma unroll
                    for (int x=0;x<4;x++) s[mi][j][x]=0.f;
            const uint32_t kb = sb + FK_B + cb*9216 + lofs;
#pragma unroll
            for (int c=0;c<4;c++){
                uint32_t kf[8][2];
#pragma unroll
                for (int jp=0;jp<4;jp++)
                    LDSM4(kf[2*jp][0],kf[2*jp][1],kf[2*jp+1][0],kf[2*jp+1][1], kb + jp*2304 + c*32);
#pragma unroll
                for (int mi=0;mi<2;mi++)
#pragma unroll
                    for (int j=0;j<8;j++)
                        HMMA(s[mi][j], qf[mi][c], kf[j][0], kf[j][1]);
            }

            // ---- softmax in f16x2 ----
            const uint32_t* mbU = smU + cb*32;
            uint32_t pp[2][8][2];
#pragma unroll
            for (int mi=0;mi<2;mi++)
#pragma unroll
                for (int j=0;j<8;j++){
                    uint32_t mb2u = mbU[j*4 + q4];
                    pp[mi][j][0] = ex2h2(hadd2(h2pack(s[mi][j][0], s[mi][j][1]), mb2u));
                    pp[mi][j][1] = ex2h2(hadd2(h2pack(s[mi][j][2], s[mi][j][3]), mb2u));
                }

            // ---- O += P V (V fragments shared); rowsum += P·1 ----
            const uint32_t vb = sb + FV_B + cb*9216 + lofsv;
#pragma unroll
            for (int c=0;c<4;c++){
                uint32_t vf[8][2];
#pragma unroll
                for (int jp=0;jp<4;jp++)
                    LDSM4_T(vf[2*jp][0],vf[2*jp][1],vf[2*jp+1][0],vf[2*jp+1][1], vb + c*2304 + jp*32);
#pragma unroll
                for (int mi=0;mi<2;mi++){
                    uint32_t A[4] = {pp[mi][2*c][0], pp[mi][2*c][1], pp[mi][2*c+1][0], pp[mi][2*c+1][1]};
#pragma unroll
                    for (int jn=0;jn<8;jn++)
                        HMMA(o[mi][jn], A, vf[jn][0], vf[jn][1]);
                    HMMA(racc[mi], A, ONESH2, ONESH2);
                }
            }
        }

        if (i < 62){
            const int pb = (cb+2>2)? cb-1 : cb+2;
            f_loadK(sb, bh, i+2, tid, pb);
            f_loadV(sb, bh, i+2, tid, pb);
            f_loadMB(sb, b, i+2, tid, pb);
        }
        CP_COMMIT();
        cb = (cb+1==3)? 0 : cb+1;
    }

    // ---- epilogue ----
#pragma unroll
    for (int mi=0;mi<2;mi++){
        const float inv0 = 1.0f/racc[mi][0], inv1 = 1.0f/racc[mi][2];
        const int row0 = q0 + wid*32 + mi*16 + g;
        __half* d0 = g_ctxh + ((size_t)(b*SEQ + row0  ))*EMB + h*HD;
        __half* d1 = g_ctxh + ((size_t)(b*SEQ + row0+8))*EMB + h*HD;
#pragma unroll
        for (int jn=0;jn<8;jn++){
            *(__half2*)(d0 + jn*8 + 2*q4) = __floats2half2_rn(o[mi][jn][0]*inv0, o[mi][jn][1]*inv0);
            *(__half2*)(d1 + jn*8 + 2*q4) = __floats2half2_rn(o[mi][jn][2]*inv1, o[mi][jn][3]*inv1);
        }
    }
}

// ---------------- launch ----------------
extern "C" void kernel_launch(void* const* d_in, const int* in_sizes, int n_in,
                              void* d_out, int out_size)
{
    const float* query=(const float*)d_in[0];
    const float* key_ =(const float*)d_in[1];
    const float* value=(const float*)d_in[2];
    const float* Wq=(const float*)d_in[3];  const float* bq=(const float*)d_in[4];
    const float* Wk=(const float*)d_in[5];  const float* bk=(const float*)d_in[6];
    const float* Wv=(const float*)d_in[7];  const float* bv=(const float*)d_in[8];
    const float* Wo=(const float*)d_in[9];  const float* bo=(const float*)d_in[10];
    const unsigned char* mask=(const unsigned char*)d_in[11];

    __half *Wh,*Ch;
    cudaGetSymbolAddress((void**)&Wh, g_Wh);
    cudaGetSymbolAddress((void**)&Ch, g_ctxh);

    cudaFuncSetAttribute(flash_h,   cudaFuncAttributeMaxDynamicSharedMemorySize, FSMEM);
    cudaFuncSetAttribute(hgemm_qkv, cudaFuncAttributeMaxDynamicSharedMemorySize, HG_SMEM);
    cudaFuncSetAttribute(hgemm_one, cudaFuncAttributeMaxDynamicSharedMemorySize, HG_SMEM);

    convert_all<<<(NIN+NW+NT+255)/256 + 1,256>>>(query, key_, value, Wq, Wk, Wv, Wo, mask);

    hgemm_qkv<<<dim3(EMB/128, NROWS/128, 3),128,HG_SMEM>>>(bq, bk, bv);

    rope_h<<<(BHTOT*SEQ*16+255)/256,256>>>();

    flash_h<<<dim3(SEQ/128, BHTOT), 128, FSMEM>>>();

    hgemm_one<<<dim3(EMB/128, NROWS/128),128,HG_SMEM>>>(Ch, Wh + 3*(size_t)WE, bo, d_out, 1);
}